// round 1
// baseline (speedup 1.0000x reference)
#include <cuda_runtime.h>
#include <math.h>

#define NEG_SLOPE 0.2f
#define MAXN 50000
#define MAXE 850000
#define F1   512
#define HH   4
#define HD   64
#define HF   256   // HH*HD
#define C2   40

// ---------------- scratch (static device globals; no allocation) -------------
__device__ int   g_is64;
__device__ int   g_src[MAXE];
__device__ int   g_dst[MAXE];
__device__ float g_h1 [MAXN * HF];      // x @ W1
__device__ float g_out1[MAXN * HF];     // layer-1 aggregated output / post-ELU h
__device__ float g_als1[MAXN * HH];
__device__ float g_ald1[MAXN * HH];
__device__ float g_m1  [MAXN * HH];
__device__ float g_den1[MAXN * HH];
__device__ float g_e1  [MAXE * HH];
__device__ float g_h2  [MAXN * C2];     // h @ W2
__device__ float g_als2[MAXN];
__device__ float g_ald2[MAXN];
__device__ float g_m2  [MAXN];
__device__ float g_den2[MAXN];
__device__ float g_e2  [MAXE];

// ---------------- helpers ----------------------------------------------------
__device__ __forceinline__ void atomicMaxFloat(float* addr, float value) {
    // standard sign-split trick; addr initialized to -inf (0xff800000)
    if (value >= 0.0f) {
        atomicMax((int*)addr, __float_as_int(value));
    } else {
        atomicMin((unsigned int*)addr, __float_as_uint(value));
    }
}

// ---------------- edge-index dtype handling ----------------------------------
__global__ void detect_dtype_kernel(const int* ei32) {
    if (threadIdx.x == 0 && blockIdx.x == 0) {
        int is64 = 1;
        #pragma unroll
        for (int i = 1; i < 64; i += 2) {
            if (ei32[i] != 0) { is64 = 0; break; }
        }
        g_is64 = is64;
    }
}

__global__ void convert_edges_kernel(const void* ei, int E) {
    int i = blockIdx.x * blockDim.x + threadIdx.x;
    if (i >= E) return;
    if (g_is64) {
        const long long* p = (const long long*)ei;
        g_src[i] = (int)p[i];
        g_dst[i] = (int)p[(long long)E + i];
    } else {
        const int* p = (const int*)ei;
        g_src[i] = p[i];
        g_dst[i] = p[E + i];
    }
}

// ---------------- init -------------------------------------------------------
__global__ void init_state_kernel(float* out, int n) {
    int i = blockIdx.x * blockDim.x + threadIdx.x;
    int tot = n * HF;
    if (i < tot) g_out1[i] = 0.0f;
    if (i < n * C2) out[i] = 0.0f;
    if (i < n * HH) {
        g_m1[i] = __int_as_float(0xff800000);
        g_den1[i] = 0.0f;
    }
    if (i < n) {
        g_m2[i] = __int_as_float(0xff800000);
        g_den2[i] = 0.0f;
    }
}

// ---------------- simple tiled SGEMM (C = A[MxK] * B[KxN]) -------------------
// BM=BN=64, BK=16, 256 threads, 4x4 micro-tile. K must be a multiple of 16.
__global__ void sgemm64_kernel(const float* __restrict__ A,
                               const float* __restrict__ B,
                               float* __restrict__ C,
                               int M, int N, int K) {
    __shared__ float As[64][17];
    __shared__ float Bs[16][64];
    const int tx = threadIdx.x % 16;
    const int ty = threadIdx.x / 16;
    const int rowBase = blockIdx.y * 64;
    const int colBase = blockIdx.x * 64;

    float acc[4][4] = {};

    for (int k0 = 0; k0 < K; k0 += 16) {
        for (int i = threadIdx.x; i < 64 * 16; i += 256) {
            int r = i / 16, c = i % 16;
            float v = 0.0f;
            if (rowBase + r < M) v = A[(size_t)(rowBase + r) * K + k0 + c];
            As[r][c] = v;
        }
        for (int i = threadIdx.x; i < 16 * 64; i += 256) {
            int r = i / 64, c = i % 64;
            float v = 0.0f;
            if (colBase + c < N) v = B[(size_t)(k0 + r) * N + colBase + c];
            Bs[r][c] = v;
        }
        __syncthreads();
        #pragma unroll
        for (int k = 0; k < 16; k++) {
            float a[4], b[4];
            #pragma unroll
            for (int i = 0; i < 4; i++) a[i] = As[ty * 4 + i][k];
            #pragma unroll
            for (int j = 0; j < 4; j++) b[j] = Bs[k][tx * 4 + j];
            #pragma unroll
            for (int i = 0; i < 4; i++)
                #pragma unroll
                for (int j = 0; j < 4; j++)
                    acc[i][j] += a[i] * b[j];
        }
        __syncthreads();
    }

    #pragma unroll
    for (int i = 0; i < 4; i++) {
        int r = rowBase + ty * 4 + i;
        if (r >= M) continue;
        #pragma unroll
        for (int j = 0; j < 4; j++) {
            int c = colBase + tx * 4 + j;
            if (c < N) C[(size_t)r * N + c] = acc[i][j];
        }
    }
}

// ---------------- layer 1 ----------------------------------------------------
__global__ void node_scores_l1_kernel(const float* __restrict__ a_s,
                                      const float* __restrict__ a_d, int n) {
    int t = blockIdx.x * blockDim.x + threadIdx.x;
    if (t >= n * HH) return;
    int node = t / HH, h = t % HH;
    const float* hr = &g_h1[node * HF + h * HD];
    float s = 0.0f, d = 0.0f;
    #pragma unroll 8
    for (int k = 0; k < HD; k++) {
        float v = hr[k];
        s += v * a_s[h * HD + k];
        d += v * a_d[h * HD + k];
    }
    g_als1[t] = s;
    g_ald1[t] = d;
}

__global__ void edge_pass1_l1_kernel(int E) {
    int i = blockIdx.x * blockDim.x + threadIdx.x;
    if (i >= E) return;
    int s = g_src[i], d = g_dst[i];
    #pragma unroll
    for (int h = 0; h < HH; h++) {
        float v = g_als1[s * HH + h] + g_ald1[d * HH + h];
        v = (v > 0.0f) ? v : NEG_SLOPE * v;
        g_e1[(size_t)i * HH + h] = v;
        atomicMaxFloat(&g_m1[d * HH + h], v);
    }
}

__global__ void edge_pass2_l1_kernel(int E) {
    int i = blockIdx.x * blockDim.x + threadIdx.x;
    if (i >= E) return;
    int d = g_dst[i];
    #pragma unroll
    for (int h = 0; h < HH; h++) {
        float v = g_e1[(size_t)i * HH + h];
        float ex = __expf(v - g_m1[d * HH + h]);
        g_e1[(size_t)i * HH + h] = ex;
        atomicAdd(&g_den1[d * HH + h], ex);
    }
}

// one warp per (edge, head); 64 dims => 2 elements per lane
__global__ void edge_aggr_l1_kernel(int E) {
    int w = (int)((blockIdx.x * (long long)blockDim.x + threadIdx.x) >> 5);
    int lane = threadIdx.x & 31;
    if (w >= E * HH) return;
    int i = w >> 2, h = w & 3;
    int s = g_src[i], d = g_dst[i];
    float alpha = g_e1[(size_t)i * HH + h] / (g_den1[d * HH + h] + 1e-16f);
    int bs = s * HF + h * HD;
    int bd = d * HF + h * HD;
    atomicAdd(&g_out1[bd + lane],      g_h1[bs + lane]      * alpha);
    atomicAdd(&g_out1[bd + lane + 32], g_h1[bs + lane + 32] * alpha);
}

__global__ void bias_elu_kernel(const float* __restrict__ b1, int n) {
    int i = blockIdx.x * blockDim.x + threadIdx.x;
    if (i >= n * HF) return;
    float v = g_out1[i] + b1[i & (HF - 1)];
    g_out1[i] = (v > 0.0f) ? v : (__expf(v) - 1.0f);
}

// ---------------- layer 2 ----------------------------------------------------
__global__ void node_scores_l2_kernel(const float* __restrict__ a_s,
                                      const float* __restrict__ a_d, int n) {
    int t = blockIdx.x * blockDim.x + threadIdx.x;
    if (t >= n) return;
    const float* hr = &g_h2[t * C2];
    float s = 0.0f, d = 0.0f;
    #pragma unroll 8
    for (int k = 0; k < C2; k++) {
        float v = hr[k];
        s += v * a_s[k];
        d += v * a_d[k];
    }
    g_als2[t] = s;
    g_ald2[t] = d;
}

__global__ void edge_pass1_l2_kernel(int E) {
    int i = blockIdx.x * blockDim.x + threadIdx.x;
    if (i >= E) return;
    int s = g_src[i], d = g_dst[i];
    float v = g_als2[s] + g_ald2[d];
    v = (v > 0.0f) ? v : NEG_SLOPE * v;
    g_e2[i] = v;
    atomicMaxFloat(&g_m2[d], v);
}

__global__ void edge_pass2_l2_kernel(int E) {
    int i = blockIdx.x * blockDim.x + threadIdx.x;
    if (i >= E) return;
    int d = g_dst[i];
    float ex = __expf(g_e2[i] - g_m2[d]);
    g_e2[i] = ex;
    atomicAdd(&g_den2[d], ex);
}

// one warp per edge; 40 dims
__global__ void edge_aggr_l2_kernel(float* __restrict__ out, int E) {
    int w = (int)((blockIdx.x * (long long)blockDim.x + threadIdx.x) >> 5);
    int lane = threadIdx.x & 31;
    if (w >= E) return;
    int s = g_src[w], d = g_dst[w];
    float alpha = g_e2[w] / (g_den2[d] + 1e-16f);
    atomicAdd(&out[d * C2 + lane], g_h2[s * C2 + lane] * alpha);
    if (lane < C2 - 32)
        atomicAdd(&out[d * C2 + 32 + lane], g_h2[s * C2 + 32 + lane] * alpha);
}

// one warp per node: +b2, log_softmax over 40 classes, in place
__global__ void final_logsoftmax_kernel(float* __restrict__ out,
                                        const float* __restrict__ b2, int n) {
    int w = (int)((blockIdx.x * (long long)blockDim.x + threadIdx.x) >> 5);
    int lane = threadIdx.x & 31;
    if (w >= n) return;
    float* row = out + (size_t)w * C2;
    float e0 = row[lane] + b2[lane];
    float e1 = (lane < C2 - 32) ? (row[32 + lane] + b2[32 + lane])
                                : __int_as_float(0xff800000);
    float m = fmaxf(e0, e1);
    #pragma unroll
    for (int o = 16; o > 0; o >>= 1) m = fmaxf(m, __shfl_xor_sync(0xffffffff, m, o));
    float se = __expf(e0 - m) + ((lane < C2 - 32) ? __expf(e1 - m) : 0.0f);
    #pragma unroll
    for (int o = 16; o > 0; o >>= 1) se += __shfl_xor_sync(0xffffffff, se, o);
    float lse = m + logf(se);
    row[lane] = e0 - lse;
    if (lane < C2 - 32) row[32 + lane] = e1 - lse;
}

// ---------------- launch -----------------------------------------------------
extern "C" void kernel_launch(void* const* d_in, const int* in_sizes, int n_in,
                              void* d_out, int out_size) {
    const float* x   = (const float*)d_in[0];
    const void*  ei  = d_in[1];
    const float* W1  = (const float*)d_in[2];
    const float* as1 = (const float*)d_in[3];
    const float* ad1 = (const float*)d_in[4];
    const float* b1  = (const float*)d_in[5];
    const float* W2  = (const float*)d_in[6];
    const float* as2 = (const float*)d_in[7];
    const float* ad2 = (const float*)d_in[8];
    const float* b2  = (const float*)d_in[9];
    float* out = (float*)d_out;

    const int n = in_sizes[0] / F1;     // 50000
    const int E = in_sizes[1] / 2;      // 850000

    float *p_h1, *p_out1, *p_h2;
    cudaGetSymbolAddress((void**)&p_h1,   g_h1);
    cudaGetSymbolAddress((void**)&p_out1, g_out1);
    cudaGetSymbolAddress((void**)&p_h2,   g_h2);

    const int T = 256;

    // edge index conversion (int32 vs int64 detection)
    detect_dtype_kernel<<<1, 32>>>((const int*)ei);
    convert_edges_kernel<<<(E + T - 1) / T, T>>>(ei, E);

    // per-launch state init (graph replays must reset accumulators)
    init_state_kernel<<<(n * HF + T - 1) / T, T>>>(out, n);

    // ---- layer 1 ----
    {
        dim3 grid((HF + 63) / 64, (n + 63) / 64);
        sgemm64_kernel<<<grid, 256>>>(x, W1, p_h1, n, HF, F1);
    }
    node_scores_l1_kernel<<<(n * HH + T - 1) / T, T>>>(as1, ad1, n);
    edge_pass1_l1_kernel<<<(E + T - 1) / T, T>>>(E);
    edge_pass2_l1_kernel<<<(E + T - 1) / T, T>>>(E);
    {
        long long warps = (long long)E * HH;
        long long thr = warps * 32;
        edge_aggr_l1_kernel<<<(unsigned)((thr + T - 1) / T), T>>>(E);
    }
    bias_elu_kernel<<<(n * HF + T - 1) / T, T>>>(b1, n);

    // ---- layer 2 ----
    {
        dim3 grid((C2 + 63) / 64, (n + 63) / 64);
        sgemm64_kernel<<<grid, 256>>>(p_out1, W2, p_h2, n, C2, HF);
    }
    node_scores_l2_kernel<<<(n + T - 1) / T, T>>>(as2, ad2, n);
    edge_pass1_l2_kernel<<<(E + T - 1) / T, T>>>(E);
    edge_pass2_l2_kernel<<<(E + T - 1) / T, T>>>(E);
    {
        long long thr = (long long)E * 32;
        edge_aggr_l2_kernel<<<(unsigned)((thr + T - 1) / T), T>>>(out, E);
    }
    final_logsoftmax_kernel<<<(n * 32 + T - 1) / T, T>>>(out, b2, n);
}

// round 2
// speedup vs baseline: 1.9934x; 1.9934x over previous
#include <cuda_runtime.h>
#include <math.h>

#define NEG_SLOPE 0.2f
#define MAXN 50000
#define MAXE 850000
#define F1   512
#define HH   4
#define HD   64
#define HF   256   // HH*HD
#define C2   40

// ---------------- scratch (static device globals; no allocation) -------------
__device__ int   g_is64;
__device__ int   g_src[MAXE];
__device__ int   g_dst[MAXE];
__device__ __align__(16) float g_h1 [MAXN * HF];      // x @ W1
__device__ __align__(16) float g_out1[MAXN * HF];     // layer-1 output / post-ELU h
__device__ __align__(16) float g_als1[MAXN * HH];
__device__ __align__(16) float g_ald1[MAXN * HH];
__device__ __align__(16) float g_m1  [MAXN * HH];
__device__ __align__(16) float g_den1[MAXN * HH];
__device__ __align__(16) float g_e1  [MAXE * HH];
__device__ __align__(16) float g_h2  [MAXN * C2];     // h @ W2
__device__ float g_als2[MAXN];
__device__ float g_ald2[MAXN];
__device__ float g_m2  [MAXN];
__device__ float g_den2[MAXN];
__device__ float g_e2  [MAXE];

// ---------------- helpers ----------------------------------------------------
__device__ __forceinline__ void atomicMaxFloat(float* addr, float value) {
    if (value >= 0.0f) {
        atomicMax((int*)addr, __float_as_int(value));
    } else {
        atomicMin((unsigned int*)addr, __float_as_uint(value));
    }
}

// sm_90+ vector reduction: one 16B atomic add instead of 4 scalar ones
__device__ __forceinline__ void redAdd4(float* p, float4 v) {
    asm volatile("red.global.add.v4.f32 [%0], {%1,%2,%3,%4};"
                 :: "l"(p), "f"(v.x), "f"(v.y), "f"(v.z), "f"(v.w) : "memory");
}

// ---------------- edge-index dtype handling ----------------------------------
__global__ void detect_dtype_kernel(const int* ei32) {
    if (threadIdx.x == 0 && blockIdx.x == 0) {
        int is64 = 1;
        #pragma unroll
        for (int i = 1; i < 64; i += 2) {
            if (ei32[i] != 0) { is64 = 0; break; }
        }
        g_is64 = is64;
    }
}

__global__ void convert_edges_kernel(const void* ei, int E) {
    int i = blockIdx.x * blockDim.x + threadIdx.x;
    if (i >= E) return;
    if (g_is64) {
        const long long* p = (const long long*)ei;
        g_src[i] = (int)p[i];
        g_dst[i] = (int)p[(long long)E + i];
    } else {
        const int* p = (const int*)ei;
        g_src[i] = p[i];
        g_dst[i] = p[E + i];
    }
}

// ---------------- init -------------------------------------------------------
__global__ void init_state_kernel(float* out, int n) {
    int i = blockIdx.x * blockDim.x + threadIdx.x;
    int tot = n * HF;
    if (i < tot) g_out1[i] = 0.0f;
    if (i < n * C2) out[i] = 0.0f;
    if (i < n * HH) {
        g_m1[i] = __int_as_float(0xff800000);
        g_den1[i] = 0.0f;
    }
    if (i < n) {
        g_m2[i] = __int_as_float(0xff800000);
        g_den2[i] = 0.0f;
    }
}

// ---------------- SGEMM 128x128, BK=16, 8x8 micro, 256 threads ---------------
// C[MxN] = A[MxK] * B[KxN]; requires K%16==0, N%128==0 (used for GEMM1, N=256)
__global__ __launch_bounds__(256, 2)
void sgemm128_kernel(const float* __restrict__ A,
                     const float* __restrict__ B,
                     float* __restrict__ C,
                     int M, int N, int K) {
    __shared__ float As[16][128];   // transposed: As[k][m]
    __shared__ float Bs[16][128];   // Bs[k][n]
    const int tid = threadIdx.x;
    const int tm = tid / 16;        // 0..15
    const int tn = tid % 16;        // 0..15
    const int rowBase = blockIdx.y * 128;
    const int colBase = blockIdx.x * 128;

    float acc[8][8] = {};

    for (int k0 = 0; k0 < K; k0 += 16) {
        // A tile: 128 rows x 16 k -> 512 float4, 2 per thread, store transposed
        #pragma unroll
        for (int j = 0; j < 2; j++) {
            int idx = tid * 2 + j;          // 0..511
            int r = idx >> 2;               // 0..127
            int cs = (idx & 3) * 4;         // 0,4,8,12
            float4 v = make_float4(0.f, 0.f, 0.f, 0.f);
            int gr = rowBase + r;
            if (gr < M) v = *(const float4*)&A[(size_t)gr * K + k0 + cs];
            As[cs + 0][r] = v.x;
            As[cs + 1][r] = v.y;
            As[cs + 2][r] = v.z;
            As[cs + 3][r] = v.w;
        }
        // B tile: 16 k x 128 n -> 512 float4, 2 per thread
        #pragma unroll
        for (int j = 0; j < 2; j++) {
            int idx = tid * 2 + j;
            int r = idx >> 5;               // 0..15
            int c = (idx & 31) * 4;         // 0..124
            float4 v = *(const float4*)&B[(size_t)(k0 + r) * N + colBase + c];
            *(float4*)&Bs[r][c] = v;
        }
        __syncthreads();

        #pragma unroll
        for (int k = 0; k < 16; k++) {
            float4 a0 = *(float4*)&As[k][tm * 4];
            float4 a1 = *(float4*)&As[k][tm * 4 + 64];
            float4 b0 = *(float4*)&Bs[k][tn * 4];
            float4 b1 = *(float4*)&Bs[k][tn * 4 + 64];
            float a[8] = {a0.x, a0.y, a0.z, a0.w, a1.x, a1.y, a1.z, a1.w};
            float b[8] = {b0.x, b0.y, b0.z, b0.w, b1.x, b1.y, b1.z, b1.w};
            #pragma unroll
            for (int i = 0; i < 8; i++)
                #pragma unroll
                for (int j = 0; j < 8; j++)
                    acc[i][j] += a[i] * b[j];
        }
        __syncthreads();
    }

    #pragma unroll
    for (int i = 0; i < 8; i++) {
        int r = rowBase + tm * 4 + (i & 3) + (i >> 2) * 64;
        if (r >= M) continue;
        int ri = (i & 3) + (i >> 2) * 4;    // acc row index
        #pragma unroll
        for (int jj = 0; jj < 2; jj++) {
            int c = colBase + tn * 4 + jj * 64;
            float4 v = make_float4(acc[ri][jj * 4 + 0], acc[ri][jj * 4 + 1],
                                   acc[ri][jj * 4 + 2], acc[ri][jj * 4 + 3]);
            *(float4*)&C[(size_t)r * N + c] = v;
        }
    }
}

// ---------------- small SGEMM (kept for GEMM2: 64x64, N=40) ------------------
__global__ void sgemm64_kernel(const float* __restrict__ A,
                               const float* __restrict__ B,
                               float* __restrict__ C,
                               int M, int N, int K) {
    __shared__ float As[64][17];
    __shared__ float Bs[16][64];
    const int tx = threadIdx.x % 16;
    const int ty = threadIdx.x / 16;
    const int rowBase = blockIdx.y * 64;
    const int colBase = blockIdx.x * 64;

    float acc[4][4] = {};

    for (int k0 = 0; k0 < K; k0 += 16) {
        for (int i = threadIdx.x; i < 64 * 16; i += 256) {
            int r = i / 16, c = i % 16;
            float v = 0.0f;
            if (rowBase + r < M) v = A[(size_t)(rowBase + r) * K + k0 + c];
            As[r][c] = v;
        }
        for (int i = threadIdx.x; i < 16 * 64; i += 256) {
            int r = i / 64, c = i % 64;
            float v = 0.0f;
            if (colBase + c < N) v = B[(size_t)(k0 + r) * N + colBase + c];
            Bs[r][c] = v;
        }
        __syncthreads();
        #pragma unroll
        for (int k = 0; k < 16; k++) {
            float a[4], b[4];
            #pragma unroll
            for (int i = 0; i < 4; i++) a[i] = As[ty * 4 + i][k];
            #pragma unroll
            for (int j = 0; j < 4; j++) b[j] = Bs[k][tx * 4 + j];
            #pragma unroll
            for (int i = 0; i < 4; i++)
                #pragma unroll
                for (int j = 0; j < 4; j++)
                    acc[i][j] += a[i] * b[j];
        }
        __syncthreads();
    }

    #pragma unroll
    for (int i = 0; i < 4; i++) {
        int r = rowBase + ty * 4 + i;
        if (r >= M) continue;
        #pragma unroll
        for (int j = 0; j < 4; j++) {
            int c = colBase + tx * 4 + j;
            if (c < N) C[(size_t)r * N + c] = acc[i][j];
        }
    }
}

// ---------------- layer 1 ----------------------------------------------------
__global__ void node_scores_l1_kernel(const float* __restrict__ a_s,
                                      const float* __restrict__ a_d, int n) {
    int t = blockIdx.x * blockDim.x + threadIdx.x;
    if (t >= n * HH) return;
    int node = t / HH, h = t % HH;
    const float4* hr = (const float4*)&g_h1[node * HF + h * HD];
    const float4* as4 = (const float4*)&a_s[h * HD];
    const float4* ad4 = (const float4*)&a_d[h * HD];
    float s = 0.0f, d = 0.0f;
    #pragma unroll
    for (int k = 0; k < HD / 4; k++) {
        float4 v = hr[k], a = as4[k], b = ad4[k];
        s += v.x * a.x + v.y * a.y + v.z * a.z + v.w * a.w;
        d += v.x * b.x + v.y * b.y + v.z * b.z + v.w * b.w;
    }
    g_als1[t] = s;
    g_ald1[t] = d;
}

__global__ void edge_pass1_l1_kernel(int E) {
    int i = blockIdx.x * blockDim.x + threadIdx.x;
    if (i >= E) return;
    int s = g_src[i], d = g_dst[i];
    float4 a = *(const float4*)&g_als1[s * HH];
    float4 b = *(const float4*)&g_ald1[d * HH];
    float4 v;
    v.x = a.x + b.x; v.y = a.y + b.y; v.z = a.z + b.z; v.w = a.w + b.w;
    v.x = (v.x > 0.f) ? v.x : NEG_SLOPE * v.x;
    v.y = (v.y > 0.f) ? v.y : NEG_SLOPE * v.y;
    v.z = (v.z > 0.f) ? v.z : NEG_SLOPE * v.z;
    v.w = (v.w > 0.f) ? v.w : NEG_SLOPE * v.w;
    *(float4*)&g_e1[(size_t)i * HH] = v;
    atomicMaxFloat(&g_m1[d * HH + 0], v.x);
    atomicMaxFloat(&g_m1[d * HH + 1], v.y);
    atomicMaxFloat(&g_m1[d * HH + 2], v.z);
    atomicMaxFloat(&g_m1[d * HH + 3], v.w);
}

__global__ void edge_pass2_l1_kernel(int E) {
    int i = blockIdx.x * blockDim.x + threadIdx.x;
    if (i >= E) return;
    int d = g_dst[i];
    float4 v = *(const float4*)&g_e1[(size_t)i * HH];
    float4 m = *(const float4*)&g_m1[d * HH];
    float4 ex;
    ex.x = __expf(v.x - m.x);
    ex.y = __expf(v.y - m.y);
    ex.z = __expf(v.z - m.z);
    ex.w = __expf(v.w - m.w);
    *(float4*)&g_e1[(size_t)i * HH] = ex;
    redAdd4(&g_den1[d * HH], ex);
}

// one warp per edge; each lane does 2 float4 chunks (256 floats total)
__global__ void edge_aggr_l1_kernel(int E) {
    int w = (int)((blockIdx.x * (long long)blockDim.x + threadIdx.x) >> 5);
    int lane = threadIdx.x & 31;
    if (w >= E) return;
    int s = g_src[w], d = g_dst[w];
    const float* e1r = &g_e1[(size_t)w * HH];
    const float* dnr = &g_den1[d * HH];
    int bs = s * HF, bd = d * HF;
    #pragma unroll
    for (int half = 0; half < 2; half++) {
        int c = lane + half * 32;         // float4 chunk index 0..63
        int h = c >> 4;                   // head = c*4/64
        float alpha = e1r[h] / (dnr[h] + 1e-16f);
        float4 v = *(const float4*)&g_h1[bs + c * 4];
        v.x *= alpha; v.y *= alpha; v.z *= alpha; v.w *= alpha;
        redAdd4(&g_out1[bd + c * 4], v);
    }
}

__global__ void bias_elu_kernel(const float* __restrict__ b1, int n) {
    int i = blockIdx.x * blockDim.x + threadIdx.x;
    if (i >= n * HF / 4) return;
    float4 v = *(const float4*)&g_out1[i * 4];
    const float4 b = *(const float4*)&b1[(i * 4) & (HF - 1)];
    v.x += b.x; v.y += b.y; v.z += b.z; v.w += b.w;
    v.x = (v.x > 0.f) ? v.x : (__expf(v.x) - 1.0f);
    v.y = (v.y > 0.f) ? v.y : (__expf(v.y) - 1.0f);
    v.z = (v.z > 0.f) ? v.z : (__expf(v.z) - 1.0f);
    v.w = (v.w > 0.f) ? v.w : (__expf(v.w) - 1.0f);
    *(float4*)&g_out1[i * 4] = v;
}

// ---------------- layer 2 ----------------------------------------------------
__global__ void node_scores_l2_kernel(const float* __restrict__ a_s,
                                      const float* __restrict__ a_d, int n) {
    int t = blockIdx.x * blockDim.x + threadIdx.x;
    if (t >= n) return;
    const float* hr = &g_h2[t * C2];
    float s = 0.0f, d = 0.0f;
    #pragma unroll 8
    for (int k = 0; k < C2; k++) {
        float v = hr[k];
        s += v * a_s[k];
        d += v * a_d[k];
    }
    g_als2[t] = s;
    g_ald2[t] = d;
}

__global__ void edge_pass1_l2_kernel(int E) {
    int i = blockIdx.x * blockDim.x + threadIdx.x;
    if (i >= E) return;
    int s = g_src[i], d = g_dst[i];
    float v = g_als2[s] + g_ald2[d];
    v = (v > 0.0f) ? v : NEG_SLOPE * v;
    g_e2[i] = v;
    atomicMaxFloat(&g_m2[d], v);
}

__global__ void edge_pass2_l2_kernel(int E) {
    int i = blockIdx.x * blockDim.x + threadIdx.x;
    if (i >= E) return;
    int d = g_dst[i];
    float ex = __expf(g_e2[i] - g_m2[d]);
    g_e2[i] = ex;
    atomicAdd(&g_den2[d], ex);
}

// thread per (edge, float4-chunk); 10 chunks cover 40 dims
__global__ void edge_aggr_l2_kernel(float* __restrict__ out, int E) {
    long long t = blockIdx.x * (long long)blockDim.x + threadIdx.x;
    if (t >= (long long)E * 10) return;
    int i = (int)(t / 10);
    int c = (int)(t % 10);
    int s = g_src[i], d = g_dst[i];
    float alpha = g_e2[i] / (g_den2[d] + 1e-16f);
    float4 v = *(const float4*)&g_h2[s * C2 + c * 4];
    v.x *= alpha; v.y *= alpha; v.z *= alpha; v.w *= alpha;
    redAdd4(&out[d * C2 + c * 4], v);
}

// one warp per node: +b2, log_softmax over 40 classes, in place
__global__ void final_logsoftmax_kernel(float* __restrict__ out,
                                        const float* __restrict__ b2, int n) {
    int w = (int)((blockIdx.x * (long long)blockDim.x + threadIdx.x) >> 5);
    int lane = threadIdx.x & 31;
    if (w >= n) return;
    float* row = out + (size_t)w * C2;
    float e0 = row[lane] + b2[lane];
    float e1 = (lane < C2 - 32) ? (row[32 + lane] + b2[32 + lane])
                                : __int_as_float(0xff800000);
    float m = fmaxf(e0, e1);
    #pragma unroll
    for (int o = 16; o > 0; o >>= 1) m = fmaxf(m, __shfl_xor_sync(0xffffffff, m, o));
    float se = __expf(e0 - m) + ((lane < C2 - 32) ? __expf(e1 - m) : 0.0f);
    #pragma unroll
    for (int o = 16; o > 0; o >>= 1) se += __shfl_xor_sync(0xffffffff, se, o);
    float lse = m + logf(se);
    row[lane] = e0 - lse;
    if (lane < C2 - 32) row[32 + lane] = e1 - lse;
}

// ---------------- launch -----------------------------------------------------
extern "C" void kernel_launch(void* const* d_in, const int* in_sizes, int n_in,
                              void* d_out, int out_size) {
    const float* x   = (const float*)d_in[0];
    const void*  ei  = d_in[1];
    const float* W1  = (const float*)d_in[2];
    const float* as1 = (const float*)d_in[3];
    const float* ad1 = (const float*)d_in[4];
    const float* b1  = (const float*)d_in[5];
    const float* W2  = (const float*)d_in[6];
    const float* as2 = (const float*)d_in[7];
    const float* ad2 = (const float*)d_in[8];
    const float* b2  = (const float*)d_in[9];
    float* out = (float*)d_out;

    const int n = in_sizes[0] / F1;     // 50000
    const int E = in_sizes[1] / 2;      // 850000

    float *p_h1, *p_out1, *p_h2;
    cudaGetSymbolAddress((void**)&p_h1,   g_h1);
    cudaGetSymbolAddress((void**)&p_out1, g_out1);
    cudaGetSymbolAddress((void**)&p_h2,   g_h2);

    const int T = 256;

    detect_dtype_kernel<<<1, 32>>>((const int*)ei);
    convert_edges_kernel<<<(E + T - 1) / T, T>>>(ei, E);
    init_state_kernel<<<(n * HF + T - 1) / T, T>>>(out, n);

    // ---- layer 1 ----
    {
        dim3 grid(HF / 128, (n + 127) / 128);
        sgemm128_kernel<<<grid, 256>>>(x, W1, p_h1, n, HF, F1);
    }
    node_scores_l1_kernel<<<(n * HH + T - 1) / T, T>>>(as1, ad1, n);
    edge_pass1_l1_kernel<<<(E + T - 1) / T, T>>>(E);
    edge_pass2_l1_kernel<<<(E + T - 1) / T, T>>>(E);
    {
        long long thr = (long long)E * 32;
        edge_aggr_l1_kernel<<<(unsigned)((thr + T - 1) / T), T>>>(E);
    }
    bias_elu_kernel<<<(n * HF / 4 + T - 1) / T, T>>>(b1, n);

    // ---- layer 2 ----
    {
        dim3 grid((C2 + 63) / 64, (n + 63) / 64);
        sgemm64_kernel<<<grid, 256>>>(p_out1, W2, p_h2, n, C2, HF);
    }
    node_scores_l2_kernel<<<(n + T - 1) / T, T>>>(as2, ad2, n);
    edge_pass1_l2_kernel<<<(E + T - 1) / T, T>>>(E);
    edge_pass2_l2_kernel<<<(E + T - 1) / T, T>>>(E);
    {
        long long thr = (long long)E * 10;
        edge_aggr_l2_kernel<<<(unsigned)((thr + T - 1) / T), T>>>(out, E);
    }
    final_logsoftmax_kernel<<<(n * 32 + T - 1) / T, T>>>(out, b2, n);
}

// round 5
// speedup vs baseline: 2.1555x; 1.0813x over previous
#include <cuda_runtime.h>
#include <stdint.h>
#include <math.h>

#define NEG_SLOPE 0.2f
#define MAXN 50000
#define MAXE 850000
#define F1   512
#define HH   4
#define HD   64
#define HF   256   // HH*HD
#define C2   40

// ---------------- scratch (static device globals; no allocation) -------------
__device__ int   g_is64;
__device__ int   g_src[MAXE];
__device__ int   g_dst[MAXE];
__device__ __align__(16) float g_h1 [MAXN * HF];      // x @ W1
__device__ __align__(16) float g_out1[MAXN * HF];     // layer-1 aggregate (pre-bias)
__device__ __align__(16) float g_als1[MAXN * HH];
__device__ __align__(16) float g_ald1[MAXN * HH];
__device__ __align__(16) float g_den1[MAXN * HH];
__device__ __align__(16) float g_e1  [MAXE * HH];
__device__ __align__(16) float g_h2  [MAXN * C2];     // elu(out1+b1) @ W2
__device__ float g_als2[MAXN];
__device__ float g_ald2[MAXN];
__device__ float g_den2[MAXN];
__device__ float g_e2  [MAXE];

// ---------------- helpers ----------------------------------------------------
__device__ __forceinline__ void redAdd4(float* p, float4 v) {
    asm volatile("red.global.add.v4.f32 [%0], {%1,%2,%3,%4};"
                 :: "l"(p), "f"(v.x), "f"(v.y), "f"(v.z), "f"(v.w) : "memory");
}

__device__ __forceinline__ void cpAsync16(unsigned int smem, const void* gmem) {
    asm volatile("cp.async.ca.shared.global [%0], [%1], 16;"
                 :: "r"(smem), "l"(gmem));
}
__device__ __forceinline__ void cpAsyncCommit() {
    asm volatile("cp.async.commit_group;");
}
__device__ __forceinline__ void cpAsyncWait0() {
    asm volatile("cp.async.wait_group 0;");
}

// ---------------- edge-index dtype handling ----------------------------------
__global__ void detect_dtype_kernel(const int* ei32) {
    if (threadIdx.x == 0 && blockIdx.x == 0) {
        int is64 = 1;
        #pragma unroll
        for (int i = 1; i < 64; i += 2) {
            if (ei32[i] != 0) { is64 = 0; break; }
        }
        g_is64 = is64;
    }
}

__global__ void convert_edges_kernel(const void* ei, int E) {
    int i = blockIdx.x * blockDim.x + threadIdx.x;
    if (i >= E) return;
    if (g_is64) {
        const long long* p = (const long long*)ei;
        g_src[i] = (int)p[i];
        g_dst[i] = (int)p[(long long)E + i];
    } else {
        const int* p = (const int*)ei;
        g_src[i] = p[i];
        g_dst[i] = p[E + i];
    }
}

// ---------------- init -------------------------------------------------------
__global__ void init_state_kernel(float* out, int n) {
    int i = blockIdx.x * blockDim.x + threadIdx.x;
    if (i < n * HF) g_out1[i] = 0.0f;
    if (i < n * C2) out[i] = 0.0f;
    if (i < n * HH) g_den1[i] = 0.0f;
    if (i < n) g_den2[i] = 0.0f;
}

// ---------------- SGEMM 128x128, BK=16, double-buffered ----------------------
// C[MxN] = A[MxK] * B[KxN]; requires K%16==0, N%128==0 (GEMM1: N=256, K=512)
__global__ __launch_bounds__(256, 2)
void sgemm128_db_kernel(const float* __restrict__ A,
                        const float* __restrict__ B,
                        float* __restrict__ C,
                        int M, int N, int K) {
    __shared__ float As[2][16][128];   // transposed: As[buf][k][m]
    __shared__ float Bs[2][16][128];   // Bs[buf][k][n]
    const int tid = threadIdx.x;
    const int tm = tid / 16;
    const int tn = tid % 16;
    const int rowBase = blockIdx.y * 128;
    const int colBase = blockIdx.x * 128;

    // per-thread load coordinates
    const int ar0 = (tid * 2)     >> 2;
    const int ac0 = ((tid * 2)     & 3) * 4;
    const int ar1 = (tid * 2 + 1) >> 2;
    const int ac1 = ((tid * 2 + 1) & 3) * 4;
    const int br0 = (tid * 2)     >> 5;
    const int bc0 = ((tid * 2)     & 31) * 4;
    const int br1 = (tid * 2 + 1) >> 5;
    const int bc1 = ((tid * 2 + 1) & 31) * 4;

    float4 pa0, pa1;            // A prefetch registers

    auto loadA = [&](int k0) {
        pa0 = make_float4(0.f, 0.f, 0.f, 0.f);
        pa1 = make_float4(0.f, 0.f, 0.f, 0.f);
        int gr0 = rowBase + ar0, gr1 = rowBase + ar1;
        if (gr0 < M) pa0 = *(const float4*)&A[(size_t)gr0 * K + k0 + ac0];
        if (gr1 < M) pa1 = *(const float4*)&A[(size_t)gr1 * K + k0 + ac1];
    };
    auto storeA = [&](int buf) {
        As[buf][ac0 + 0][ar0] = pa0.x;
        As[buf][ac0 + 1][ar0] = pa0.y;
        As[buf][ac0 + 2][ar0] = pa0.z;
        As[buf][ac0 + 3][ar0] = pa0.w;
        As[buf][ac1 + 0][ar1] = pa1.x;
        As[buf][ac1 + 1][ar1] = pa1.y;
        As[buf][ac1 + 2][ar1] = pa1.z;
        As[buf][ac1 + 3][ar1] = pa1.w;
    };
    auto loadB = [&](int k0, int buf) {
        unsigned int s0 = (unsigned int)__cvta_generic_to_shared(&Bs[buf][br0][bc0]);
        unsigned int s1 = (unsigned int)__cvta_generic_to_shared(&Bs[buf][br1][bc1]);
        cpAsync16(s0, &B[(size_t)(k0 + br0) * N + colBase + bc0]);
        cpAsync16(s1, &B[(size_t)(k0 + br1) * N + colBase + bc1]);
    };

    float acc[8][8] = {};

    // prologue: stage 0
    loadA(0);
    loadB(0, 0);
    storeA(0);
    cpAsyncCommit();
    cpAsyncWait0();
    __syncthreads();

    const int nStages = K / 16;
    for (int st = 0; st < nStages; st++) {
        int buf = st & 1;
        int nbuf = buf ^ 1;
        bool more = (st + 1) < nStages;
        if (more) {
            loadA((st + 1) * 16);
            loadB((st + 1) * 16, nbuf);
            cpAsyncCommit();
        }

        #pragma unroll
        for (int k = 0; k < 16; k++) {
            float4 a0 = *(float4*)&As[buf][k][tm * 4];
            float4 a1 = *(float4*)&As[buf][k][tm * 4 + 64];
            float4 b0 = *(float4*)&Bs[buf][k][tn * 4];
            float4 b1 = *(float4*)&Bs[buf][k][tn * 4 + 64];
            float a[8] = {a0.x, a0.y, a0.z, a0.w, a1.x, a1.y, a1.z, a1.w};
            float b[8] = {b0.x, b0.y, b0.z, b0.w, b1.x, b1.y, b1.z, b1.w};
            #pragma unroll
            for (int i = 0; i < 8; i++)
                #pragma unroll
                for (int j = 0; j < 8; j++)
                    acc[i][j] += a[i] * b[j];
        }

        if (more) {
            storeA(nbuf);
            cpAsyncWait0();
        }
        __syncthreads();
    }

    #pragma unroll
    for (int i = 0; i < 8; i++) {
        int r = rowBase + tm * 4 + (i & 3) + (i >> 2) * 64;
        if (r >= M) continue;
        int ri = (i & 3) + (i >> 2) * 4;
        #pragma unroll
        for (int jj = 0; jj < 2; jj++) {
            int c = colBase + tn * 4 + jj * 64;
            float4 v = make_float4(acc[ri][jj * 4 + 0], acc[ri][jj * 4 + 1],
                                   acc[ri][jj * 4 + 2], acc[ri][jj * 4 + 3]);
            *(float4*)&C[(size_t)r * N + c] = v;
        }
    }
}

// ---------------- GEMM2: 64x64 tiles, fused elu(A + b1) on the A path --------
__global__ void sgemm64_elu_kernel(const float* __restrict__ A,
                                   const float* __restrict__ b1,
                                   const float* __restrict__ B,
                                   float* __restrict__ C,
                                   int M, int N, int K) {
    __shared__ float As[64][17];
    __shared__ float Bs[16][64];
    const int tx = threadIdx.x % 16;
    const int ty = threadIdx.x / 16;
    const int rowBase = blockIdx.y * 64;
    const int colBase = blockIdx.x * 64;

    float acc[4][4] = {};

    for (int k0 = 0; k0 < K; k0 += 16) {
        for (int i = threadIdx.x; i < 64 * 16; i += 256) {
            int r = i / 16, c = i % 16;
            float v = 0.0f;
            if (rowBase + r < M) {
                v = A[(size_t)(rowBase + r) * K + k0 + c] + b1[k0 + c];
                v = (v > 0.f) ? v : (__expf(v) - 1.0f);
            }
            As[r][c] = v;
        }
        for (int i = threadIdx.x; i < 16 * 64; i += 256) {
            int r = i / 64, c = i % 64;
            float v = 0.0f;
            if (colBase + c < N) v = B[(size_t)(k0 + r) * N + colBase + c];
            Bs[r][c] = v;
        }
        __syncthreads();
        #pragma unroll
        for (int k = 0; k < 16; k++) {
            float a[4], b[4];
            #pragma unroll
            for (int i = 0; i < 4; i++) a[i] = As[ty * 4 + i][k];
            #pragma unroll
            for (int j = 0; j < 4; j++) b[j] = Bs[k][tx * 4 + j];
            #pragma unroll
            for (int i = 0; i < 4; i++)
                #pragma unroll
                for (int j = 0; j < 4; j++)
                    acc[i][j] += a[i] * b[j];
        }
        __syncthreads();
    }

    #pragma unroll
    for (int i = 0; i < 4; i++) {
        int r = rowBase + ty * 4 + i;
        if (r >= M) continue;
        #pragma unroll
        for (int j = 0; j < 4; j++) {
            int c = colBase + tx * 4 + j;
            if (c < N) C[(size_t)r * N + c] = acc[i][j];
        }
    }
}

// ---------------- layer 1 ----------------------------------------------------
__global__ void node_scores_l1_kernel(const float* __restrict__ a_s,
                                      const float* __restrict__ a_d, int n) {
    int t = blockIdx.x * blockDim.x + threadIdx.x;
    if (t >= n * HH) return;
    int node = t / HH, h = t % HH;
    const float4* hr = (const float4*)&g_h1[node * HF + h * HD];
    const float4* as4 = (const float4*)&a_s[h * HD];
    const float4* ad4 = (const float4*)&a_d[h * HD];
    float s = 0.0f, d = 0.0f;
    #pragma unroll
    for (int k = 0; k < HD / 4; k++) {
        float4 v = hr[k], a = as4[k], b = ad4[k];
        s += v.x * a.x + v.y * a.y + v.z * a.z + v.w * a.w;
        d += v.x * b.x + v.y * b.y + v.z * b.z + v.w * b.w;
    }
    g_als1[t] = s;
    g_ald1[t] = d;
}

// fused: e = leaky(als+ald); ex = exp(e) (no max shift - args bounded);
// store ex; accumulate denominator
__global__ void edge_soft_l1_kernel(int E) {
    int i = blockIdx.x * blockDim.x + threadIdx.x;
    if (i >= E) return;
    int s = g_src[i], d = g_dst[i];
    float4 a = *(const float4*)&g_als1[s * HH];
    float4 b = *(const float4*)&g_ald1[d * HH];
    float4 v;
    v.x = a.x + b.x; v.y = a.y + b.y; v.z = a.z + b.z; v.w = a.w + b.w;
    v.x = (v.x > 0.f) ? v.x : NEG_SLOPE * v.x;
    v.y = (v.y > 0.f) ? v.y : NEG_SLOPE * v.y;
    v.z = (v.z > 0.f) ? v.z : NEG_SLOPE * v.z;
    v.w = (v.w > 0.f) ? v.w : NEG_SLOPE * v.w;
    float4 ex;
    ex.x = __expf(v.x); ex.y = __expf(v.y);
    ex.z = __expf(v.z); ex.w = __expf(v.w);
    *(float4*)&g_e1[(size_t)i * HH] = ex;
    redAdd4(&g_den1[d * HH], ex);
}

// one warp per edge; each lane does 2 float4 chunks (256 floats total)
__global__ void edge_aggr_l1_kernel(int E) {
    int w = (int)((blockIdx.x * (long long)blockDim.x + threadIdx.x) >> 5);
    int lane = threadIdx.x & 31;
    if (w >= E) return;
    int s = g_src[w], d = g_dst[w];
    const float* e1r = &g_e1[(size_t)w * HH];
    const float* dnr = &g_den1[d * HH];
    int bs = s * HF, bd = d * HF;
    #pragma unroll
    for (int half = 0; half < 2; half++) {
        int c = lane + half * 32;
        int h = c >> 4;
        float alpha = e1r[h] / (dnr[h] + 1e-16f);
        float4 v = *(const float4*)&g_h1[bs + c * 4];
        v.x *= alpha; v.y *= alpha; v.z *= alpha; v.w *= alpha;
        redAdd4(&g_out1[bd + c * 4], v);
    }
}

// ---------------- layer 2 ----------------------------------------------------
__global__ void node_scores_l2_kernel(const float* __restrict__ a_s,
                                      const float* __restrict__ a_d, int n) {
    int t = blockIdx.x * blockDim.x + threadIdx.x;
    if (t >= n) return;
    const float* hr = &g_h2[t * C2];
    float s = 0.0f, d = 0.0f;
    #pragma unroll 8
    for (int k = 0; k < C2; k++) {
        float v = hr[k];
        s += v * a_s[k];
        d += v * a_d[k];
    }
    g_als2[t] = s;
    g_ald2[t] = d;
}

__global__ void edge_soft_l2_kernel(int E) {
    int i = blockIdx.x * blockDim.x + threadIdx.x;
    if (i >= E) return;
    int s = g_src[i], d = g_dst[i];
    float v = g_als2[s] + g_ald2[d];
    v = (v > 0.0f) ? v : NEG_SLOPE * v;
    float ex = __expf(v);
    g_e2[i] = ex;
    atomicAdd(&g_den2[d], ex);
}

// thread per (edge, float4-chunk); 10 chunks cover 40 dims
__global__ void edge_aggr_l2_kernel(float* __restrict__ out, int E) {
    long long t = blockIdx.x * (long long)blockDim.x + threadIdx.x;
    if (t >= (long long)E * 10) return;
    int i = (int)(t / 10);
    int c = (int)(t % 10);
    int s = g_src[i], d = g_dst[i];
    float alpha = g_e2[i] / (g_den2[d] + 1e-16f);
    float4 v = *(const float4*)&g_h2[s * C2 + c * 4];
    v.x *= alpha; v.y *= alpha; v.z *= alpha; v.w *= alpha;
    redAdd4(&out[d * C2 + c * 4], v);
}

// one warp per node: +b2, log_softmax over 40 classes, in place
__global__ void final_logsoftmax_kernel(float* __restrict__ out,
                                        const float* __restrict__ b2, int n) {
    int w = (int)((blockIdx.x * (long long)blockDim.x + threadIdx.x) >> 5);
    int lane = threadIdx.x & 31;
    if (w >= n) return;
    float* row = out + (size_t)w * C2;
    float e0 = row[lane] + b2[lane];
    float e1 = (lane < C2 - 32) ? (row[32 + lane] + b2[32 + lane])
                                : __int_as_float(0xff800000);
    float m = fmaxf(e0, e1);
    #pragma unroll
    for (int o = 16; o > 0; o >>= 1) m = fmaxf(m, __shfl_xor_sync(0xffffffff, m, o));
    float se = __expf(e0 - m) + ((lane < C2 - 32) ? __expf(e1 - m) : 0.0f);
    #pragma unroll
    for (int o = 16; o > 0; o >>= 1) se += __shfl_xor_sync(0xffffffff, se, o);
    float lse = m + logf(se);
    row[lane] = e0 - lse;
    if (lane < C2 - 32) row[32 + lane] = e1 - lse;
}

// ---------------- launch -----------------------------------------------------
extern "C" void kernel_launch(void* const* d_in, const int* in_sizes, int n_in,
                              void* d_out, int out_size) {
    const float* x   = (const float*)d_in[0];
    const void*  ei  = d_in[1];
    const float* W1  = (const float*)d_in[2];
    const float* as1 = (const float*)d_in[3];
    const float* ad1 = (const float*)d_in[4];
    const float* b1  = (const float*)d_in[5];
    const float* W2  = (const float*)d_in[6];
    const float* as2 = (const float*)d_in[7];
    const float* ad2 = (const float*)d_in[8];
    const float* b2  = (const float*)d_in[9];
    float* out = (float*)d_out;

    const int n = in_sizes[0] / F1;     // 50000
    const int E = in_sizes[1] / 2;      // 850000

    float *p_h1, *p_out1, *p_h2;
    cudaGetSymbolAddress((void**)&p_h1,   g_h1);
    cudaGetSymbolAddress((void**)&p_out1, g_out1);
    cudaGetSymbolAddress((void**)&p_h2,   g_h2);

    const int T = 256;

    detect_dtype_kernel<<<1, 32>>>((const int*)ei);
    convert_edges_kernel<<<(E + T - 1) / T, T>>>(ei, E);
    init_state_kernel<<<(n * HF + T - 1) / T, T>>>(out, n);

    // ---- layer 1 ----
    {
        dim3 grid(HF / 128, (n + 127) / 128);
        sgemm128_db_kernel<<<grid, 256>>>(x, W1, p_h1, n, HF, F1);
    }
    node_scores_l1_kernel<<<(n * HH + T - 1) / T, T>>>(as1, ad1, n);
    edge_soft_l1_kernel<<<(E + T - 1) / T, T>>>(E);
    {
        long long thr = (long long)E * 32;
        edge_aggr_l1_kernel<<<(unsigned)((thr + T - 1) / T), T>>>(E);
    }

    // ---- layer 2 (bias+ELU fused into GEMM2 A-load) ----
    {
        dim3 grid((C2 + 63) / 64, (n + 63) / 64);
        sgemm64_elu_kernel<<<grid, 256>>>(p_out1, b1, W2, p_h2, n, C2, HF);
    }
    node_scores_l2_kernel<<<(n + T - 1) / T, T>>>(as2, ad2, n);
    edge_soft_l2_kernel<<<(E + T - 1) / T, T>>>(E);
    {
        long long thr = (long long)E * 10;
        edge_aggr_l2_kernel<<<(unsigned)((thr + T - 1) / T), T>>>(out, E);
    }
    final_logsoftmax_kernel<<<(n * 32 + T - 1) / T, T>>>(out, b2, n);
}

// round 9
// speedup vs baseline: 2.4064x; 1.1164x over previous
#include <cuda_runtime.h>
#include <stdint.h>
#include <math.h>

#define NEG_SLOPE 0.2f
#define MAXN 50000
#define MAXE 850000
#define F1   512
#define HH   4
#define HD   64
#define HF   256   // HH*HD
#define C2   40

// ---------------- scratch (static device globals; no allocation) -------------
__device__ int   g_is64;
__device__ int   g_src[MAXE];
__device__ int   g_dst[MAXE];
__device__ int   g_cnt[MAXN];
__device__ int   g_rowptr[MAXN + 1];
__device__ int   g_cursor[MAXN];
__device__ int   g_csr_src[MAXE];
__device__ int   g_csr_dst[MAXE];
__device__ __align__(16) float g_h1 [MAXN * HF];      // x @ W1
__device__ __align__(16) float g_out1[MAXN * HF];     // layer-1 aggregate (pre-bias)
__device__ __align__(16) float g_als1[MAXN * HH];
__device__ __align__(16) float g_ald1[MAXN * HH];
__device__ __align__(16) float g_e1  [MAXE * HH];     // exp(leaky(...)) in CSR order
__device__ __align__(16) float g_h2  [MAXN * C2];     // elu(out1+b1) @ W2
__device__ float g_als2[MAXN];
__device__ float g_ald2[MAXN];
__device__ float g_e2  [MAXE];                        // CSR order

// ---------------- helpers ----------------------------------------------------
__device__ __forceinline__ void cpAsync16(unsigned int smem, const void* gmem) {
    asm volatile("cp.async.ca.shared.global [%0], [%1], 16;"
                 :: "r"(smem), "l"(gmem));
}
__device__ __forceinline__ void cpAsyncCommit() {
    asm volatile("cp.async.commit_group;");
}
__device__ __forceinline__ void cpAsyncWait0() {
    asm volatile("cp.async.wait_group 0;");
}

// ---------------- edge-index dtype handling + CSR build ----------------------
__global__ void detect_dtype_kernel(const int* ei32) {
    if (threadIdx.x == 0 && blockIdx.x == 0) {
        int is64 = 1;
        #pragma unroll
        for (int i = 1; i < 64; i += 2) {
            if (ei32[i] != 0) { is64 = 0; break; }
        }
        g_is64 = is64;
    }
}

__global__ void zero_cnt_kernel(int n) {
    int i = blockIdx.x * blockDim.x + threadIdx.x;
    if (i < n) g_cnt[i] = 0;
}

// convert + histogram of destinations
__global__ void convert_edges_kernel(const void* ei, int E) {
    int i = blockIdx.x * blockDim.x + threadIdx.x;
    if (i >= E) return;
    int s, d;
    if (g_is64) {
        const long long* p = (const long long*)ei;
        s = (int)p[i];
        d = (int)p[(long long)E + i];
    } else {
        const int* p = (const int*)ei;
        s = p[i];
        d = p[E + i];
    }
    g_src[i] = s;
    g_dst[i] = d;
    atomicAdd(&g_cnt[d], 1);
}

// single block, 1024 threads: exclusive scan of g_cnt -> g_rowptr, g_cursor
__global__ void build_rowptr_kernel(int n) {
    __shared__ int sums[1024];
    const int t = threadIdx.x;
    const int CH = (n + 1023) / 1024;
    int start = t * CH;
    int end = start + CH; if (end > n) end = n;
    int s = 0;
    for (int i = start; i < end; i++) s += g_cnt[i];
    sums[t] = s;
    __syncthreads();
    // Hillis-Steele inclusive scan
    for (int d = 1; d < 1024; d <<= 1) {
        int v = (t >= d) ? sums[t - d] : 0;
        __syncthreads();
        sums[t] += v;
        __syncthreads();
    }
    int off = (t == 0) ? 0 : sums[t - 1];
    for (int i = start; i < end; i++) {
        g_rowptr[i] = off;
        g_cursor[i] = off;
        off += g_cnt[i];
    }
    if (end == n && start <= n) {
        if (t == 1023 || end == n) g_rowptr[n] = sums[1023];
    }
}

__global__ void scatter_kernel(int E) {
    int i = blockIdx.x * blockDim.x + threadIdx.x;
    if (i >= E) return;
    int d = g_dst[i];
    int pos = atomicAdd(&g_cursor[d], 1);
    g_csr_src[pos] = g_src[i];
    g_csr_dst[pos] = d;
}

// ---------------- SGEMM 128x128, BK=16, double-buffered ----------------------
__global__ __launch_bounds__(256, 2)
void sgemm128_db_kernel(const float* __restrict__ A,
                        const float* __restrict__ B,
                        float* __restrict__ C,
                        int M, int N, int K) {
    __shared__ float As[2][16][128];
    __shared__ float Bs[2][16][128];
    const int tid = threadIdx.x;
    const int tm = tid / 16;
    const int tn = tid % 16;
    const int rowBase = blockIdx.y * 128;
    const int colBase = blockIdx.x * 128;

    const int ar0 = (tid * 2)     >> 2;
    const int ac0 = ((tid * 2)     & 3) * 4;
    const int ar1 = (tid * 2 + 1) >> 2;
    const int ac1 = ((tid * 2 + 1) & 3) * 4;
    const int br0 = (tid * 2)     >> 5;
    const int bc0 = ((tid * 2)     & 31) * 4;
    const int br1 = (tid * 2 + 1) >> 5;
    const int bc1 = ((tid * 2 + 1) & 31) * 4;

    float4 pa0, pa1;

    auto loadA = [&](int k0) {
        pa0 = make_float4(0.f, 0.f, 0.f, 0.f);
        pa1 = make_float4(0.f, 0.f, 0.f, 0.f);
        int gr0 = rowBase + ar0, gr1 = rowBase + ar1;
        if (gr0 < M) pa0 = *(const float4*)&A[(size_t)gr0 * K + k0 + ac0];
        if (gr1 < M) pa1 = *(const float4*)&A[(size_t)gr1 * K + k0 + ac1];
    };
    auto storeA = [&](int buf) {
        As[buf][ac0 + 0][ar0] = pa0.x;
        As[buf][ac0 + 1][ar0] = pa0.y;
        As[buf][ac0 + 2][ar0] = pa0.z;
        As[buf][ac0 + 3][ar0] = pa0.w;
        As[buf][ac1 + 0][ar1] = pa1.x;
        As[buf][ac1 + 1][ar1] = pa1.y;
        As[buf][ac1 + 2][ar1] = pa1.z;
        As[buf][ac1 + 3][ar1] = pa1.w;
    };
    auto loadB = [&](int k0, int buf) {
        unsigned int s0 = (unsigned int)__cvta_generic_to_shared(&Bs[buf][br0][bc0]);
        unsigned int s1 = (unsigned int)__cvta_generic_to_shared(&Bs[buf][br1][bc1]);
        cpAsync16(s0, &B[(size_t)(k0 + br0) * N + colBase + bc0]);
        cpAsync16(s1, &B[(size_t)(k0 + br1) * N + colBase + bc1]);
    };

    float acc[8][8] = {};

    loadA(0);
    loadB(0, 0);
    storeA(0);
    cpAsyncCommit();
    cpAsyncWait0();
    __syncthreads();

    const int nStages = K / 16;
    for (int st = 0; st < nStages; st++) {
        int buf = st & 1;
        int nbuf = buf ^ 1;
        bool more = (st + 1) < nStages;
        if (more) {
            loadA((st + 1) * 16);
            loadB((st + 1) * 16, nbuf);
            cpAsyncCommit();
        }

        #pragma unroll
        for (int k = 0; k < 16; k++) {
            float4 a0 = *(float4*)&As[buf][k][tm * 4];
            float4 a1 = *(float4*)&As[buf][k][tm * 4 + 64];
            float4 b0 = *(float4*)&Bs[buf][k][tn * 4];
            float4 b1 = *(float4*)&Bs[buf][k][tn * 4 + 64];
            float a[8] = {a0.x, a0.y, a0.z, a0.w, a1.x, a1.y, a1.z, a1.w};
            float b[8] = {b0.x, b0.y, b0.z, b0.w, b1.x, b1.y, b1.z, b1.w};
            #pragma unroll
            for (int i = 0; i < 8; i++)
                #pragma unroll
                for (int j = 0; j < 8; j++)
                    acc[i][j] += a[i] * b[j];
        }

        if (more) {
            storeA(nbuf);
            cpAsyncWait0();
        }
        __syncthreads();
    }

    #pragma unroll
    for (int i = 0; i < 8; i++) {
        int r = rowBase + tm * 4 + (i & 3) + (i >> 2) * 64;
        if (r >= M) continue;
        int ri = (i & 3) + (i >> 2) * 4;
        #pragma unroll
        for (int jj = 0; jj < 2; jj++) {
            int c = colBase + tn * 4 + jj * 64;
            float4 v = make_float4(acc[ri][jj * 4 + 0], acc[ri][jj * 4 + 1],
                                   acc[ri][jj * 4 + 2], acc[ri][jj * 4 + 3]);
            *(float4*)&C[(size_t)r * N + c] = v;
        }
    }
}

// ---------------- GEMM2: 64x64 tiles, fused elu(A + b1) on the A path --------
__global__ void sgemm64_elu_kernel(const float* __restrict__ A,
                                   const float* __restrict__ b1,
                                   const float* __restrict__ B,
                                   float* __restrict__ C,
                                   int M, int N, int K) {
    __shared__ float As[64][17];
    __shared__ float Bs[16][64];
    const int tx = threadIdx.x % 16;
    const int ty = threadIdx.x / 16;
    const int rowBase = blockIdx.y * 64;
    const int colBase = blockIdx.x * 64;

    float acc[4][4] = {};

    for (int k0 = 0; k0 < K; k0 += 16) {
        for (int i = threadIdx.x; i < 64 * 16; i += 256) {
            int r = i / 16, c = i % 16;
            float v = 0.0f;
            if (rowBase + r < M) {
                v = A[(size_t)(rowBase + r) * K + k0 + c] + b1[k0 + c];
                v = (v > 0.f) ? v : (__expf(v) - 1.0f);
            }
            As[r][c] = v;
        }
        for (int i = threadIdx.x; i < 16 * 64; i += 256) {
            int r = i / 64, c = i % 64;
            float v = 0.0f;
            if (colBase + c < N) v = B[(size_t)(k0 + r) * N + colBase + c];
            Bs[r][c] = v;
        }
        __syncthreads();
        #pragma unroll
        for (int k = 0; k < 16; k++) {
            float a[4], b[4];
            #pragma unroll
            for (int i = 0; i < 4; i++) a[i] = As[ty * 4 + i][k];
            #pragma unroll
            for (int j = 0; j < 4; j++) b[j] = Bs[k][tx * 4 + j];
            #pragma unroll
            for (int i = 0; i < 4; i++)
                #pragma unroll
                for (int j = 0; j < 4; j++)
                    acc[i][j] += a[i] * b[j];
        }
        __syncthreads();
    }

    #pragma unroll
    for (int i = 0; i < 4; i++) {
        int r = rowBase + ty * 4 + i;
        if (r >= M) continue;
        #pragma unroll
        for (int j = 0; j < 4; j++) {
            int c = colBase + tx * 4 + j;
            if (c < N) C[(size_t)r * N + c] = acc[i][j];
        }
    }
}

// ---------------- layer 1 ----------------------------------------------------
__global__ void node_scores_l1_kernel(const float* __restrict__ a_s,
                                      const float* __restrict__ a_d, int n) {
    int t = blockIdx.x * blockDim.x + threadIdx.x;
    if (t >= n * HH) return;
    int node = t / HH, h = t % HH;
    const float4* hr = (const float4*)&g_h1[node * HF + h * HD];
    const float4* as4 = (const float4*)&a_s[h * HD];
    const float4* ad4 = (const float4*)&a_d[h * HD];
    float s = 0.0f, d = 0.0f;
    #pragma unroll
    for (int k = 0; k < HD / 4; k++) {
        float4 v = hr[k], a = as4[k], b = ad4[k];
        s += v.x * a.x + v.y * a.y + v.z * a.z + v.w * a.w;
        d += v.x * b.x + v.y * b.y + v.z * b.z + v.w * b.w;
    }
    g_als1[t] = s;
    g_ald1[t] = d;
}

// per CSR position: ex = exp(leaky(als[s]+ald[d])), stored in CSR order
__global__ void edge_soft_l1_kernel(int E) {
    int i = blockIdx.x * blockDim.x + threadIdx.x;
    if (i >= E) return;
    int s = g_csr_src[i], d = g_csr_dst[i];
    float4 a = *(const float4*)&g_als1[s * HH];
    float4 b = *(const float4*)&g_ald1[d * HH];
    float4 v;
    v.x = a.x + b.x; v.y = a.y + b.y; v.z = a.z + b.z; v.w = a.w + b.w;
    v.x = (v.x > 0.f) ? v.x : NEG_SLOPE * v.x;
    v.y = (v.y > 0.f) ? v.y : NEG_SLOPE * v.y;
    v.z = (v.z > 0.f) ? v.z : NEG_SLOPE * v.z;
    v.w = (v.w > 0.f) ? v.w : NEG_SLOPE * v.w;
    float4 ex;
    ex.x = __expf(v.x); ex.y = __expf(v.y);
    ex.z = __expf(v.z); ex.w = __expf(v.w);
    *(float4*)&g_e1[(size_t)i * HH] = ex;
}

// one warp per node: denominator + aggregation, register-resident, no atomics
__global__ void node_aggr_l1_kernel(int n) {
    int node = (int)((blockIdx.x * (long long)blockDim.x + threadIdx.x) >> 5);
    int lane = threadIdx.x & 31;
    if (node >= n) return;
    int beg = g_rowptr[node], end = g_rowptr[node + 1];

    // denominator per head
    float4 den = make_float4(0.f, 0.f, 0.f, 0.f);
    for (int j = beg + lane; j < end; j += 32) {
        float4 ex = *(const float4*)&g_e1[(size_t)j * HH];
        den.x += ex.x; den.y += ex.y; den.z += ex.z; den.w += ex.w;
    }
    #pragma unroll
    for (int o = 16; o > 0; o >>= 1) {
        den.x += __shfl_xor_sync(0xffffffffu, den.x, o);
        den.y += __shfl_xor_sync(0xffffffffu, den.y, o);
        den.z += __shfl_xor_sync(0xffffffffu, den.z, o);
        den.w += __shfl_xor_sync(0xffffffffu, den.w, o);
    }
    float4 inv;
    inv.x = 1.0f / (den.x + 1e-16f);
    inv.y = 1.0f / (den.y + 1e-16f);
    inv.z = 1.0f / (den.z + 1e-16f);
    inv.w = 1.0f / (den.w + 1e-16f);
    // lane covers chunk c0=lane (head 0/1) and c1=lane+32 (head 2/3)
    float invA = (lane < 16) ? inv.x : inv.y;
    float invB = (lane < 16) ? inv.z : inv.w;

    float4 acc0 = make_float4(0.f, 0.f, 0.f, 0.f);
    float4 acc1 = make_float4(0.f, 0.f, 0.f, 0.f);
    for (int j = beg; j < end; j++) {
        int src = g_csr_src[j];                        // broadcast
        float4 ex = *(const float4*)&g_e1[(size_t)j * HH];  // broadcast
        float aA = ((lane < 16) ? ex.x : ex.y) * invA;
        float aB = ((lane < 16) ? ex.z : ex.w) * invB;
        const float4* hp = (const float4*)&g_h1[(size_t)src * HF];
        float4 v0 = hp[lane];
        float4 v1 = hp[lane + 32];
        acc0.x += aA * v0.x; acc0.y += aA * v0.y;
        acc0.z += aA * v0.z; acc0.w += aA * v0.w;
        acc1.x += aB * v1.x; acc1.y += aB * v1.y;
        acc1.z += aB * v1.z; acc1.w += aB * v1.w;
    }
    float4* op = (float4*)&g_out1[(size_t)node * HF];
    op[lane]      = acc0;
    op[lane + 32] = acc1;
}

// ---------------- layer 2 ----------------------------------------------------
__global__ void node_scores_l2_kernel(const float* __restrict__ a_s,
                                      const float* __restrict__ a_d, int n) {
    int t = blockIdx.x * blockDim.x + threadIdx.x;
    if (t >= n) return;
    const float* hr = &g_h2[t * C2];
    float s = 0.0f, d = 0.0f;
    #pragma unroll 8
    for (int k = 0; k < C2; k++) {
        float v = hr[k];
        s += v * a_s[k];
        d += v * a_d[k];
    }
    g_als2[t] = s;
    g_ald2[t] = d;
}

__global__ void edge_soft_l2_kernel(int E) {
    int i = blockIdx.x * blockDim.x + threadIdx.x;
    if (i >= E) return;
    int s = g_csr_src[i], d = g_csr_dst[i];
    float v = g_als2[s] + g_ald2[d];
    v = (v > 0.0f) ? v : NEG_SLOPE * v;
    g_e2[i] = __expf(v);
}

// one warp per node: denominator + aggregation + bias + log_softmax
__global__ void node_aggr_l2_kernel(float* __restrict__ out,
                                    const float* __restrict__ b2, int n) {
    int node = (int)((blockIdx.x * (long long)blockDim.x + threadIdx.x) >> 5);
    int lane = threadIdx.x & 31;
    if (node >= n) return;
    int beg = g_rowptr[node], end = g_rowptr[node + 1];

    float den = 0.0f;
    for (int j = beg + lane; j < end; j += 32) den += g_e2[j];
    #pragma unroll
    for (int o = 16; o > 0; o >>= 1) den += __shfl_xor_sync(0xffffffffu, den, o);
    float inv = 1.0f / (den + 1e-16f);

    float4 acc = make_float4(0.f, 0.f, 0.f, 0.f);
    for (int j = beg; j < end; j++) {
        int src = g_csr_src[j];            // broadcast
        float alpha = g_e2[j] * inv;       // broadcast
        if (lane < C2 / 4) {
            float4 v = *(const float4*)&g_h2[(size_t)src * C2 + lane * 4];
            acc.x += alpha * v.x; acc.y += alpha * v.y;
            acc.z += alpha * v.z; acc.w += alpha * v.w;
        }
    }
    if (lane < C2 / 4) {
        float4 b = ((const float4*)b2)[lane];
        acc.x += b.x; acc.y += b.y; acc.z += b.z; acc.w += b.w;
    }
    float m = (lane < C2 / 4)
        ? fmaxf(fmaxf(acc.x, acc.y), fmaxf(acc.z, acc.w))
        : __int_as_float(0xff800000);
    #pragma unroll
    for (int o = 16; o > 0; o >>= 1) m = fmaxf(m, __shfl_xor_sync(0xffffffffu, m, o));
    float se = (lane < C2 / 4)
        ? (__expf(acc.x - m) + __expf(acc.y - m) + __expf(acc.z - m) + __expf(acc.w - m))
        : 0.0f;
    #pragma unroll
    for (int o = 16; o > 0; o >>= 1) se += __shfl_xor_sync(0xffffffffu, se, o);
    float lse = m + logf(se);
    if (lane < C2 / 4) {
        float4 r = make_float4(acc.x - lse, acc.y - lse, acc.z - lse, acc.w - lse);
        *(float4*)&out[(size_t)node * C2 + lane * 4] = r;
    }
}

// ---------------- launch -----------------------------------------------------
extern "C" void kernel_launch(void* const* d_in, const int* in_sizes, int n_in,
                              void* d_out, int out_size) {
    const float* x   = (const float*)d_in[0];
    const void*  ei  = d_in[1];
    const float* W1  = (const float*)d_in[2];
    const float* as1 = (const float*)d_in[3];
    const float* ad1 = (const float*)d_in[4];
    const float* b1  = (const float*)d_in[5];
    const float* W2  = (const float*)d_in[6];
    const float* as2 = (const float*)d_in[7];
    const float* ad2 = (const float*)d_in[8];
    const float* b2  = (const float*)d_in[9];
    float* out = (float*)d_out;

    const int n = in_sizes[0] / F1;     // 50000
    const int E = in_sizes[1] / 2;      // 850000

    float *p_h1, *p_out1, *p_h2;
    cudaGetSymbolAddress((void**)&p_h1,   g_h1);
    cudaGetSymbolAddress((void**)&p_out1, g_out1);
    cudaGetSymbolAddress((void**)&p_h2,   g_h2);

    const int T = 256;

    // ---- CSR build ----
    detect_dtype_kernel<<<1, 32>>>((const int*)ei);
    zero_cnt_kernel<<<(n + T - 1) / T, T>>>(n);
    convert_edges_kernel<<<(E + T - 1) / T, T>>>(ei, E);
    build_rowptr_kernel<<<1, 1024>>>(n);
    scatter_kernel<<<(E + T - 1) / T, T>>>(E);

    // ---- layer 1 ----
    {
        dim3 grid(HF / 128, (n + 127) / 128);
        sgemm128_db_kernel<<<grid, 256>>>(x, W1, p_h1, n, HF, F1);
    }
    node_scores_l1_kernel<<<(n * HH + T - 1) / T, T>>>(as1, ad1, n);
    edge_soft_l1_kernel<<<(E + T - 1) / T, T>>>(E);
    {
        long long thr = (long long)n * 32;
        node_aggr_l1_kernel<<<(unsigned)((thr + T - 1) / T), T>>>(n);
    }

    // ---- layer 2 (bias+ELU fused into GEMM2 A-load) ----
    {
        dim3 grid((C2 + 63) / 64, (n + 63) / 64);
        sgemm64_elu_kernel<<<grid, 256>>>(p_out1, b1, W2, p_h2, n, C2, HF);
    }
    node_scores_l2_kernel<<<(n + T - 1) / T, T>>>(as2, ad2, n);
    edge_soft_l2_kernel<<<(E + T - 1) / T, T>>>(E);
    {
        long long thr = (long long)n * 32;
        node_aggr_l2_kernel<<<(unsigned)((thr + T - 1) / T), T>>>(out, b2, n);
    }
}

// round 14
// speedup vs baseline: 2.6850x; 1.1158x over previous
#include <cuda_runtime.h>
#include <stdint.h>
#include <math.h>

#define NEG_SLOPE 0.2f
#define MAXN 50000
#define MAXE 850000
#define F1   512
#define HH   4
#define HD   64
#define HF   256   // HH*HD
#define C2   40
#define SCAN_B 1024
#define MAX_BLOCKS 64   // >= ceil(MAXN/1024) = 49

// ---------------- scratch (static device globals; no allocation) -------------
__device__ int   g_is64;
__device__ int   g_src[MAXE];
__device__ int   g_dst[MAXE];
__device__ int   g_cnt[MAXN];
__device__ int   g_rowptr[MAXN + 1];
__device__ int   g_cursor[MAXN];
__device__ int   g_csr_src[MAXE];
__device__ int   g_csr_dst[MAXE];
__device__ int   g_blocksum[MAX_BLOCKS];
__device__ int   g_blockoff[MAX_BLOCKS];
__device__ __align__(16) float g_h1 [MAXN * HF];      // x @ W1
__device__ __align__(16) float g_out1[MAXN * HF];     // layer-1 aggregate (pre-bias)
__device__ __align__(16) float g_als1[MAXN * HH];
__device__ __align__(16) float g_ald1[MAXN * HH];
__device__ __align__(16) float g_e1  [MAXE * HH];     // exp(leaky(...)) in CSR order
__device__ __align__(16) float g_h2  [MAXN * C2];     // elu(out1+b1) @ W2
__device__ float g_als2[MAXN];
__device__ float g_ald2[MAXN];
__device__ float g_e2  [MAXE];                        // CSR order

// ---------------- helpers ----------------------------------------------------
__device__ __forceinline__ void cpAsync16(unsigned int smem, const void* gmem) {
    asm volatile("cp.async.ca.shared.global [%0], [%1], 16;"
                 :: "r"(smem), "l"(gmem));
}
__device__ __forceinline__ void cpAsyncCommit() {
    asm volatile("cp.async.commit_group;");
}
__device__ __forceinline__ void cpAsyncWait0() {
    asm volatile("cp.async.wait_group 0;");
}

// ---------------- edge-index dtype handling + CSR build ----------------------
__global__ void detect_dtype_kernel(const int* ei32) {
    if (threadIdx.x == 0 && blockIdx.x == 0) {
        int is64 = 1;
        #pragma unroll
        for (int i = 1; i < 64; i += 2) {
            if (ei32[i] != 0) { is64 = 0; break; }
        }
        g_is64 = is64;
    }
}

__global__ void zero_cnt_kernel(int n) {
    int i = blockIdx.x * blockDim.x + threadIdx.x;
    if (i < n) g_cnt[i] = 0;
}

// convert + histogram of destinations
__global__ void convert_edges_kernel(const void* ei, int E) {
    int i = blockIdx.x * blockDim.x + threadIdx.x;
    if (i >= E) return;
    int s, d;
    if (g_is64) {
        const long long* p = (const long long*)ei;
        s = (int)p[i];
        d = (int)p[(long long)E + i];
    } else {
        const int* p = (const int*)ei;
        s = p[i];
        d = p[E + i];
    }
    g_src[i] = s;
    g_dst[i] = d;
    atomicAdd(&g_cnt[d], 1);
}

// ---- two-level scan: block sums -> offsets -> write --------------------------
__global__ void scan_block_sums_kernel(int n) {
    __shared__ int sh[SCAN_B];
    int i = blockIdx.x * SCAN_B + threadIdx.x;
    int v = (i < n) ? g_cnt[i] : 0;
    sh[threadIdx.x] = v;
    __syncthreads();
    for (int s = SCAN_B / 2; s > 0; s >>= 1) {
        if (threadIdx.x < s) sh[threadIdx.x] += sh[threadIdx.x + s];
        __syncthreads();
    }
    if (threadIdx.x == 0) g_blocksum[blockIdx.x] = sh[0];
}

__global__ void scan_block_offsets_kernel(int nBlocks, int n) {
    // single block, 64 threads; nBlocks <= 64
    __shared__ int sh[MAX_BLOCKS];
    int t = threadIdx.x;
    int v = (t < nBlocks) ? g_blocksum[t] : 0;
    sh[t] = v;
    __syncthreads();
    // inclusive Hillis-Steele on 64
    for (int d = 1; d < MAX_BLOCKS; d <<= 1) {
        int x = (t >= d) ? sh[t - d] : 0;
        __syncthreads();
        sh[t] += x;
        __syncthreads();
    }
    if (t < nBlocks) g_blockoff[t] = sh[t] - v;   // exclusive
    if (t == 0) g_rowptr[n] = sh[MAX_BLOCKS - 1];
}

__global__ void scan_write_kernel(int n) {
    __shared__ int sh[SCAN_B];
    int i = blockIdx.x * SCAN_B + threadIdx.x;
    int t = threadIdx.x;
    int v = (i < n) ? g_cnt[i] : 0;
    sh[t] = v;
    __syncthreads();
    // inclusive Hillis-Steele over 1024
    for (int d = 1; d < SCAN_B; d <<= 1) {
        int x = (t >= d) ? sh[t - d] : 0;
        __syncthreads();
        sh[t] += x;
        __syncthreads();
    }
    if (i < n) {
        int excl = sh[t] - v + g_blockoff[blockIdx.x];
        g_rowptr[i] = excl;
        g_cursor[i] = excl;
    }
}

__global__ void scatter_kernel(int E) {
    int i = blockIdx.x * blockDim.x + threadIdx.x;
    if (i >= E) return;
    int d = g_dst[i];
    int pos = atomicAdd(&g_cursor[d], 1);
    g_csr_src[pos] = g_src[i];
    g_csr_dst[pos] = d;
}

// ---------------- SGEMM 128x128, BK=16, double-buffered ----------------------
__global__ __launch_bounds__(256, 2)
void sgemm128_db_kernel(const float* __restrict__ A,
                        const float* __restrict__ B,
                        float* __restrict__ C,
                        int M, int N, int K) {
    __shared__ float As[2][16][128];
    __shared__ float Bs[2][16][128];
    const int tid = threadIdx.x;
    const int tm = tid / 16;
    const int tn = tid % 16;
    const int rowBase = blockIdx.y * 128;
    const int colBase = blockIdx.x * 128;

    const int ar0 = (tid * 2)     >> 2;
    const int ac0 = ((tid * 2)     & 3) * 4;
    const int ar1 = (tid * 2 + 1) >> 2;
    const int ac1 = ((tid * 2 + 1) & 3) * 4;
    const int br0 = (tid * 2)     >> 5;
    const int bc0 = ((tid * 2)     & 31) * 4;
    const int br1 = (tid * 2 + 1) >> 5;
    const int bc1 = ((tid * 2 + 1) & 31) * 4;

    float4 pa0, pa1;

    auto loadA = [&](int k0) {
        pa0 = make_float4(0.f, 0.f, 0.f, 0.f);
        pa1 = make_float4(0.f, 0.f, 0.f, 0.f);
        int gr0 = rowBase + ar0, gr1 = rowBase + ar1;
        if (gr0 < M) pa0 = *(const float4*)&A[(size_t)gr0 * K + k0 + ac0];
        if (gr1 < M) pa1 = *(const float4*)&A[(size_t)gr1 * K + k0 + ac1];
    };
    auto storeA = [&](int buf) {
        As[buf][ac0 + 0][ar0] = pa0.x;
        As[buf][ac0 + 1][ar0] = pa0.y;
        As[buf][ac0 + 2][ar0] = pa0.z;
        As[buf][ac0 + 3][ar0] = pa0.w;
        As[buf][ac1 + 0][ar1] = pa1.x;
        As[buf][ac1 + 1][ar1] = pa1.y;
        As[buf][ac1 + 2][ar1] = pa1.z;
        As[buf][ac1 + 3][ar1] = pa1.w;
    };
    auto loadB = [&](int k0, int buf) {
        unsigned int s0 = (unsigned int)__cvta_generic_to_shared(&Bs[buf][br0][bc0]);
        unsigned int s1 = (unsigned int)__cvta_generic_to_shared(&Bs[buf][br1][bc1]);
        cpAsync16(s0, &B[(size_t)(k0 + br0) * N + colBase + bc0]);
        cpAsync16(s1, &B[(size_t)(k0 + br1) * N + colBase + bc1]);
    };

    float acc[8][8] = {};

    loadA(0);
    loadB(0, 0);
    storeA(0);
    cpAsyncCommit();
    cpAsyncWait0();
    __syncthreads();

    const int nStages = K / 16;
    for (int st = 0; st < nStages; st++) {
        int buf = st & 1;
        int nbuf = buf ^ 1;
        bool more = (st + 1) < nStages;
        if (more) {
            loadA((st + 1) * 16);
            loadB((st + 1) * 16, nbuf);
            cpAsyncCommit();
        }

        #pragma unroll
        for (int k = 0; k < 16; k++) {
            float4 a0 = *(float4*)&As[buf][k][tm * 4];
            float4 a1 = *(float4*)&As[buf][k][tm * 4 + 64];
            float4 b0 = *(float4*)&Bs[buf][k][tn * 4];
            float4 b1 = *(float4*)&Bs[buf][k][tn * 4 + 64];
            float a[8] = {a0.x, a0.y, a0.z, a0.w, a1.x, a1.y, a1.z, a1.w};
            float b[8] = {b0.x, b0.y, b0.z, b0.w, b1.x, b1.y, b1.z, b1.w};
            #pragma unroll
            for (int i = 0; i < 8; i++)
                #pragma unroll
                for (int j = 0; j < 8; j++)
                    acc[i][j] += a[i] * b[j];
        }

        if (more) {
            storeA(nbuf);
            cpAsyncWait0();
        }
        __syncthreads();
    }

    #pragma unroll
    for (int i = 0; i < 8; i++) {
        int r = rowBase + tm * 4 + (i & 3) + (i >> 2) * 64;
        if (r >= M) continue;
        int ri = (i & 3) + (i >> 2) * 4;
        #pragma unroll
        for (int jj = 0; jj < 2; jj++) {
            int c = colBase + tn * 4 + jj * 64;
            float4 v = make_float4(acc[ri][jj * 4 + 0], acc[ri][jj * 4 + 1],
                                   acc[ri][jj * 4 + 2], acc[ri][jj * 4 + 3]);
            *(float4*)&C[(size_t)r * N + c] = v;
        }
    }
}

// ---------------- GEMM2: 64x64 tiles, fused elu(A + b1) on the A path --------
__global__ void sgemm64_elu_kernel(const float* __restrict__ A,
                                   const float* __restrict__ b1,
                                   const float* __restrict__ B,
                                   float* __restrict__ C,
                                   int M, int N, int K) {
    __shared__ float As[64][17];
    __shared__ float Bs[16][64];
    const int tx = threadIdx.x % 16;
    const int ty = threadIdx.x / 16;
    const int rowBase = blockIdx.y * 64;
    const int colBase = blockIdx.x * 64;

    float acc[4][4] = {};

    for (int k0 = 0; k0 < K; k0 += 16) {
        for (int i = threadIdx.x; i < 64 * 16; i += 256) {
            int r = i / 16, c = i % 16;
            float v = 0.0f;
            if (rowBase + r < M) {
                v = A[(size_t)(rowBase + r) * K + k0 + c] + b1[k0 + c];
                v = (v > 0.f) ? v : (__expf(v) - 1.0f);
            }
            As[r][c] = v;
        }
        for (int i = threadIdx.x; i < 16 * 64; i += 256) {
            int r = i / 64, c = i % 64;
            float v = 0.0f;
            if (colBase + c < N) v = B[(size_t)(k0 + r) * N + colBase + c];
            Bs[r][c] = v;
        }
        __syncthreads();
        #pragma unroll
        for (int k = 0; k < 16; k++) {
            float a[4], b[4];
            #pragma unroll
            for (int i = 0; i < 4; i++) a[i] = As[ty * 4 + i][k];
            #pragma unroll
            for (int j = 0; j < 4; j++) b[j] = Bs[k][tx * 4 + j];
            #pragma unroll
            for (int i = 0; i < 4; i++)
                #pragma unroll
                for (int j = 0; j < 4; j++)
                    acc[i][j] += a[i] * b[j];
        }
        __syncthreads();
    }

    #pragma unroll
    for (int i = 0; i < 4; i++) {
        int r = rowBase + ty * 4 + i;
        if (r >= M) continue;
        #pragma unroll
        for (int j = 0; j < 4; j++) {
            int c = colBase + tx * 4 + j;
            if (c < N) C[(size_t)r * N + c] = acc[i][j];
        }
    }
}

// ---------------- layer 1 ----------------------------------------------------
__global__ void node_scores_l1_kernel(const float* __restrict__ a_s,
                                      const float* __restrict__ a_d, int n) {
    int t = blockIdx.x * blockDim.x + threadIdx.x;
    if (t >= n * HH) return;
    int node = t / HH, h = t % HH;
    const float4* hr = (const float4*)&g_h1[node * HF + h * HD];
    const float4* as4 = (const float4*)&a_s[h * HD];
    const float4* ad4 = (const float4*)&a_d[h * HD];
    float s = 0.0f, d = 0.0f;
    #pragma unroll
    for (int k = 0; k < HD / 4; k++) {
        float4 v = hr[k], a = as4[k], b = ad4[k];
        s += v.x * a.x + v.y * a.y + v.z * a.z + v.w * a.w;
        d += v.x * b.x + v.y * b.y + v.z * b.z + v.w * b.w;
    }
    g_als1[t] = s;
    g_ald1[t] = d;
}

// per CSR position: ex = exp(leaky(als[s]+ald[d])), stored in CSR order
__global__ void edge_soft_l1_kernel(int E) {
    int i = blockIdx.x * blockDim.x + threadIdx.x;
    if (i >= E) return;
    int s = g_csr_src[i], d = g_csr_dst[i];
    float4 a = *(const float4*)&g_als1[s * HH];
    float4 b = *(const float4*)&g_ald1[d * HH];
    float4 v;
    v.x = a.x + b.x; v.y = a.y + b.y; v.z = a.z + b.z; v.w = a.w + b.w;
    v.x = (v.x > 0.f) ? v.x : NEG_SLOPE * v.x;
    v.y = (v.y > 0.f) ? v.y : NEG_SLOPE * v.y;
    v.z = (v.z > 0.f) ? v.z : NEG_SLOPE * v.z;
    v.w = (v.w > 0.f) ? v.w : NEG_SLOPE * v.w;
    float4 ex;
    ex.x = __expf(v.x); ex.y = __expf(v.y);
    ex.z = __expf(v.z); ex.w = __expf(v.w);
    *(float4*)&g_e1[(size_t)i * HH] = ex;
}

// one warp per node: denominator + aggregation, register-resident, no atomics
__global__ void node_aggr_l1_kernel(int n) {
    int node = (int)((blockIdx.x * (long long)blockDim.x + threadIdx.x) >> 5);
    int lane = threadIdx.x & 31;
    if (node >= n) return;
    int beg = g_rowptr[node], end = g_rowptr[node + 1];

    // denominator per head
    float4 den = make_float4(0.f, 0.f, 0.f, 0.f);
    for (int j = beg + lane; j < end; j += 32) {
        float4 ex = *(const float4*)&g_e1[(size_t)j * HH];
        den.x += ex.x; den.y += ex.y; den.z += ex.z; den.w += ex.w;
    }
    #pragma unroll
    for (int o = 16; o > 0; o >>= 1) {
        den.x += __shfl_xor_sync(0xffffffffu, den.x, o);
        den.y += __shfl_xor_sync(0xffffffffu, den.y, o);
        den.z += __shfl_xor_sync(0xffffffffu, den.z, o);
        den.w += __shfl_xor_sync(0xffffffffu, den.w, o);
    }
    float4 inv;
    inv.x = 1.0f / (den.x + 1e-16f);
    inv.y = 1.0f / (den.y + 1e-16f);
    inv.z = 1.0f / (den.z + 1e-16f);
    inv.w = 1.0f / (den.w + 1e-16f);
    float invA = (lane < 16) ? inv.x : inv.y;
    float invB = (lane < 16) ? inv.z : inv.w;

    float4 acc0 = make_float4(0.f, 0.f, 0.f, 0.f);
    float4 acc1 = make_float4(0.f, 0.f, 0.f, 0.f);
    for (int j = beg; j < end; j++) {
        int src = g_csr_src[j];                        // broadcast
        float4 ex = *(const float4*)&g_e1[(size_t)j * HH];  // broadcast
        float aA = ((lane < 16) ? ex.x : ex.y) * invA;
        float aB = ((lane < 16) ? ex.z : ex.w) * invB;
        const float4* hp = (const float4*)&g_h1[(size_t)src * HF];
        float4 v0 = hp[lane];
        float4 v1 = hp[lane + 32];
        acc0.x += aA * v0.x; acc0.y += aA * v0.y;
        acc0.z += aA * v0.z; acc0.w += aA * v0.w;
        acc1.x += aB * v1.x; acc1.y += aB * v1.y;
        acc1.z += aB * v1.z; acc1.w += aB * v1.w;
    }
    float4* op = (float4*)&g_out1[(size_t)node * HF];
    op[lane]      = acc0;
    op[lane + 32] = acc1;
}

// ---------------- layer 2 ----------------------------------------------------
__global__ void node_scores_l2_kernel(const float* __restrict__ a_s,
                                      const float* __restrict__ a_d, int n) {
    int t = blockIdx.x * blockDim.x + threadIdx.x;
    if (t >= n) return;
    const float* hr = &g_h2[t * C2];
    float s = 0.0f, d = 0.0f;
    #pragma unroll 8
    for (int k = 0; k < C2; k++) {
        float v = hr[k];
        s += v * a_s[k];
        d += v * a_d[k];
    }
    g_als2[t] = s;
    g_ald2[t] = d;
}

__global__ void edge_soft_l2_kernel(int E) {
    int i = blockIdx.x * blockDim.x + threadIdx.x;
    if (i >= E) return;
    int s = g_csr_src[i], d = g_csr_dst[i];
    float v = g_als2[s] + g_ald2[d];
    v = (v > 0.0f) ? v : NEG_SLOPE * v;
    g_e2[i] = __expf(v);
}

// one warp per node: denominator + aggregation + bias + log_softmax
__global__ void node_aggr_l2_kernel(float* __restrict__ out,
                                    const float* __restrict__ b2, int n) {
    int node = (int)((blockIdx.x * (long long)blockDim.x + threadIdx.x) >> 5);
    int lane = threadIdx.x & 31;
    if (node >= n) return;
    int beg = g_rowptr[node], end = g_rowptr[node + 1];

    float den = 0.0f;
    for (int j = beg + lane; j < end; j += 32) den += g_e2[j];
    #pragma unroll
    for (int o = 16; o > 0; o >>= 1) den += __shfl_xor_sync(0xffffffffu, den, o);
    float inv = 1.0f / (den + 1e-16f);

    float4 acc = make_float4(0.f, 0.f, 0.f, 0.f);
    for (int j = beg; j < end; j++) {
        int src = g_csr_src[j];            // broadcast
        float alpha = g_e2[j] * inv;       // broadcast
        if (lane < C2 / 4) {
            float4 v = *(const float4*)&g_h2[(size_t)src * C2 + lane * 4];
            acc.x += alpha * v.x; acc.y += alpha * v.y;
            acc.z += alpha * v.z; acc.w += alpha * v.w;
        }
    }
    if (lane < C2 / 4) {
        float4 b = ((const float4*)b2)[lane];
        acc.x += b.x; acc.y += b.y; acc.z += b.z; acc.w += b.w;
    }
    float m = (lane < C2 / 4)
        ? fmaxf(fmaxf(acc.x, acc.y), fmaxf(acc.z, acc.w))
        : __int_as_float(0xff800000);
    #pragma unroll
    for (int o = 16; o > 0; o >>= 1) m = fmaxf(m, __shfl_xor_sync(0xffffffffu, m, o));
    float se = (lane < C2 / 4)
        ? (__expf(acc.x - m) + __expf(acc.y - m) + __expf(acc.z - m) + __expf(acc.w - m))
        : 0.0f;
    #pragma unroll
    for (int o = 16; o > 0; o >>= 1) se += __shfl_xor_sync(0xffffffffu, se, o);
    float lse = m + logf(se);
    if (lane < C2 / 4) {
        float4 r = make_float4(acc.x - lse, acc.y - lse, acc.z - lse, acc.w - lse);
        *(float4*)&out[(size_t)node * C2 + lane * 4] = r;
    }
}

// ---------------- launch -----------------------------------------------------
extern "C" void kernel_launch(void* const* d_in, const int* in_sizes, int n_in,
                              void* d_out, int out_size) {
    const float* x   = (const float*)d_in[0];
    const void*  ei  = d_in[1];
    const float* W1  = (const float*)d_in[2];
    const float* as1 = (const float*)d_in[3];
    const float* ad1 = (const float*)d_in[4];
    const float* b1  = (const float*)d_in[5];
    const float* W2  = (const float*)d_in[6];
    const float* as2 = (const float*)d_in[7];
    const float* ad2 = (const float*)d_in[8];
    const float* b2  = (const float*)d_in[9];
    float* out = (float*)d_out;

    const int n = in_sizes[0] / F1;     // 50000
    const int E = in_sizes[1] / 2;      // 850000

    float *p_h1, *p_out1, *p_h2;
    cudaGetSymbolAddress((void**)&p_h1,   g_h1);
    cudaGetSymbolAddress((void**)&p_out1, g_out1);
    cudaGetSymbolAddress((void**)&p_h2,   g_h2);

    const int T = 256;
    const int nScanBlocks = (n + SCAN_B - 1) / SCAN_B;   // 49

    // ---- CSR build ----
    detect_dtype_kernel<<<1, 32>>>((const int*)ei);
    zero_cnt_kernel<<<(n + T - 1) / T, T>>>(n);
    convert_edges_kernel<<<(E + T - 1) / T, T>>>(ei, E);
    scan_block_sums_kernel<<<nScanBlocks, SCAN_B>>>(n);
    scan_block_offsets_kernel<<<1, MAX_BLOCKS>>>(nScanBlocks, n);
    scan_write_kernel<<<nScanBlocks, SCAN_B>>>(n);
    scatter_kernel<<<(E + T - 1) / T, T>>>(E);

    // ---- layer 1 ----
    {
        dim3 grid(HF / 128, (n + 127) / 128);
        sgemm128_db_kernel<<<grid, 256>>>(x, W1, p_h1, n, HF, F1);
    }
    node_scores_l1_kernel<<<(n * HH + T - 1) / T, T>>>(as1, ad1, n);
    edge_soft_l1_kernel<<<(E + T - 1) / T, T>>>(E);
    {
        long long thr = (long long)n * 32;
        node_aggr_l1_kernel<<<(unsigned)((thr + T - 1) / T), T>>>(n);
    }

    // ---- layer 2 (bias+ELU fused into GEMM2 A-load) ----
    {
        dim3 grid((C2 + 63) / 64, (n + 63) / 64);
        sgemm64_elu_kernel<<<grid, 256>>>(p_out1, b1, W2, p_h2, n, C2, HF);
    }
    node_scores_l2_kernel<<<(n + T - 1) / T, T>>>(as2, ad2, n);
    edge_soft_l2_kernel<<<(E + T - 1) / T, T>>>(E);
    {
        long long thr = (long long)n * 32;
        node_aggr_l2_kernel<<<(unsigned)((thr + T - 1) / T), T>>>(out, b2, n);
    }
}